// round 4
// baseline (speedup 1.0000x reference)
#include <cuda_runtime.h>
#include <math.h>

// Problem constants (fixed by setup_inputs)
#define BB    8
#define NT    14
#define NF    72
#define NTOK  1008          // NT*NF
#define DM    256
#define NH    8
#define DK    32
#define NFREQ 8             // d_rpe/2/2
#define NDT   27            // 2*NT-1
#define NDF   143           // 2*NF-1
#define TBL   (NDT*NDF)     // 3861
#define MTOT  (BB*NTOK)     // 8064
#define BH    (BB*NH)       // 64

// Scratch (device globals; module-static, no runtime allocation)
__device__ float g_table[NH * TBL];
__device__ float g_Q[BH * NTOK * DK];
__device__ float g_K[BH * NTOK * DK];
__device__ float g_V[BH * NTOK * DK];
__device__ float g_AO[MTOT * DM];

// Resolved input pointers (filled by classify_kernel on device)
__device__ const float* dp_qt;
__device__ const float* dp_kt;
__device__ const float* dp_vt;
__device__ const int*   dp_tq;
__device__ const int*   dp_fq;
__device__ const int*   dp_tk;
__device__ const int*   dp_fk;
__device__ const float* dp_Wq;
__device__ const float* dp_Wk;
__device__ const float* dp_Wv;
__device__ const float* dp_Wo;
__device__ const float* dp_Wrpe;

// ---------------------------------------------------------------------------
// 0) Classify inputs by content. Host has already bucketed by size:
//    t*: tokens (3, in encountered order), p*: positions (4), w*: 65536-weights
//    (4), wr: W_rpe. Position arrays discriminate the global ordering:
//    t_* values in [0,14) -> max<=13 ; f_* in [0,72) -> max>=14 (w.h.p.)
//    Pattern TFTF => dict-insertion order; FFTT => alphabetical order.
// ---------------------------------------------------------------------------
__global__ void classify_kernel(const float* t0, const float* t1, const float* t2,
                                const int* p0, const int* p1, const int* p2, const int* p3,
                                const float* w0, const float* w1, const float* w2, const float* w3,
                                const float* wr) {
    __shared__ int mres[4];
    int tid = threadIdx.x;
    int w = tid >> 5, lane = tid & 31;
    const int* arr = (w == 0) ? p0 : (w == 1) ? p1 : (w == 2) ? p2 : p3;
    int m = 0;
    for (int i = lane; i < NTOK; i += 32) m = max(m, arr[i]);
#pragma unroll
    for (int off = 16; off > 0; off >>= 1)
        m = max(m, __shfl_xor_sync(0xffffffffu, m, off));
    if (lane == 0) mres[w] = m;
    __syncthreads();
    if (tid == 0) {
        bool T0 = (mres[0] <= NT - 1), T1 = (mres[1] <= NT - 1);
        bool T2 = (mres[2] <= NT - 1), T3 = (mres[3] <= NT - 1);
        if (!T0 && !T1 && T2 && T3) {
            // alphabetical: f_k, f_q, t_k, t_q | k,q,v tokens | W_k,W_o,W_q,W_v
            dp_fk = p0; dp_fq = p1; dp_tk = p2; dp_tq = p3;
            dp_kt = t0; dp_qt = t1; dp_vt = t2;
            dp_Wk = w0; dp_Wo = w1; dp_Wq = w2; dp_Wv = w3;
        } else if (T0 && T1 && !T2 && !T3) {
            // grouped: t_q, t_k, f_q, f_k | assume q,k,v tokens | W_q,W_k,W_v,W_o
            dp_tq = p0; dp_tk = p1; dp_fq = p2; dp_fk = p3;
            dp_qt = t0; dp_kt = t1; dp_vt = t2;
            dp_Wq = w0; dp_Wk = w1; dp_Wv = w2; dp_Wo = w3;
        } else {
            // default / insertion: t_q, f_q, t_k, f_k | q,k,v | W_q,W_k,W_v,W_o
            dp_tq = p0; dp_fq = p1; dp_tk = p2; dp_fk = p3;
            dp_qt = t0; dp_kt = t1; dp_vt = t2;
            dp_Wq = w0; dp_Wk = w1; dp_Wv = w2; dp_Wo = w3;
        }
        dp_Wrpe = wr;
    }
}

// ---------------------------------------------------------------------------
// 1) RPE bias table: table[h][dt*NDF+df] = sine_encode_2d(rel) . W_rpe[h]
// ---------------------------------------------------------------------------
__global__ void bias_table_kernel() {
    int gid = blockIdx.x * blockDim.x + threadIdx.x;
    if (gid >= NH * TBL) return;
    int pos = gid >> 3;
    int h   = gid & 7;
    int dt  = pos / NDF;
    int df  = pos % NDF;
    float pt = (float)(dt - (NT - 1)) / (float)(NT - 1);
    float pf = (float)(df - (NF - 1)) / (float)(NF - 1);
    const float* w = dp_Wrpe + h * 32;   // d_rpe = 32
    float acc = 0.f;
    float lg = logf(10000.0f);
#pragma unroll
    for (int j = 0; j < NFREQ; j++) {
        float fr = expf(-lg * (float)j / (float)NFREQ);
        float at = pt * fr;
        float af = pf * fr;
        acc += sinf(at) * w[j];
        acc += cosf(at) * w[NFREQ + j];
        acc += sinf(af) * w[2 * NFREQ + j];
        acc += cosf(af) * w[3 * NFREQ + j];
    }
    g_table[h * TBL + pos] = acc;
}

// ---------------------------------------------------------------------------
// 2) GEMM: C[m][n] = sum_k X[m][k] * W[n][k]. 64x64 tiles, 4x4 micro-tiles.
//    sel 1/2/3: X = q/k/v tokens, W = W_q/W_k/W_v, head-split write to g_Q/K/V
//    sel 0:     X = g_AO, W = W_o, row-major write to outp (d_out)
// ---------------------------------------------------------------------------
__global__ void __launch_bounds__(256) gemm256(float* __restrict__ outp, int sel) {
    const float* X;
    const float* W;
    if      (sel == 1) { X = dp_qt; W = dp_Wq; }
    else if (sel == 2) { X = dp_kt; W = dp_Wk; }
    else if (sel == 3) { X = dp_vt; W = dp_Wv; }
    else               { X = g_AO;  W = dp_Wo; }

    __shared__ float As[16][64];
    __shared__ float Bs[16][64];
    int tid = threadIdx.x;
    int tx = tid & 15;
    int ty = tid >> 4;
    int m0 = blockIdx.y << 6;
    int n0 = blockIdx.x << 6;
    int lr = tid >> 2;            // 0..63 load row
    int lc = (tid & 3) << 2;      // 0,4,8,12

    float acc[4][4];
#pragma unroll
    for (int i = 0; i < 4; i++)
#pragma unroll
        for (int j = 0; j < 4; j++) acc[i][j] = 0.f;

    for (int k0 = 0; k0 < DM; k0 += 16) {
        float4 av = *(const float4*)(X + (size_t)(m0 + lr) * DM + k0 + lc);
        float4 bv = *(const float4*)(W + (size_t)(n0 + lr) * DM + k0 + lc);
        __syncthreads();
        As[lc + 0][lr] = av.x; As[lc + 1][lr] = av.y;
        As[lc + 2][lr] = av.z; As[lc + 3][lr] = av.w;
        Bs[lc + 0][lr] = bv.x; Bs[lc + 1][lr] = bv.y;
        Bs[lc + 2][lr] = bv.z; Bs[lc + 3][lr] = bv.w;
        __syncthreads();
#pragma unroll
        for (int k = 0; k < 16; k++) {
            float4 a = *(const float4*)&As[k][ty << 2];
            float4 b = *(const float4*)&Bs[k][tx << 2];
            acc[0][0] += a.x * b.x; acc[0][1] += a.x * b.y; acc[0][2] += a.x * b.z; acc[0][3] += a.x * b.w;
            acc[1][0] += a.y * b.x; acc[1][1] += a.y * b.y; acc[1][2] += a.y * b.z; acc[1][3] += a.y * b.w;
            acc[2][0] += a.z * b.x; acc[2][1] += a.z * b.y; acc[2][2] += a.z * b.z; acc[2][3] += a.z * b.w;
            acc[3][0] += a.w * b.x; acc[3][1] += a.w * b.y; acc[3][2] += a.w * b.z; acc[3][3] += a.w * b.w;
        }
    }

    int ncol = n0 + (tx << 2);
    if (sel == 0) {
#pragma unroll
        for (int i = 0; i < 4; i++) {
            int m = m0 + (ty << 2) + i;
            float4 o = make_float4(acc[i][0], acc[i][1], acc[i][2], acc[i][3]);
            *(float4*)(outp + (size_t)m * DM + ncol) = o;
        }
    } else {
        float* dst = (sel == 1) ? g_Q : (sel == 2) ? g_K : g_V;
        int h = ncol >> 5;
        int d = ncol & 31;
#pragma unroll
        for (int i = 0; i < 4; i++) {
            int m = m0 + (ty << 2) + i;
            int b = m / NTOK;
            int nn = m - b * NTOK;
            float4 o = make_float4(acc[i][0], acc[i][1], acc[i][2], acc[i][3]);
            *(float4*)(dst + (size_t)((b * NH + h) * NTOK + nn) * DK + d) = o;
        }
    }
}

// ---------------------------------------------------------------------------
// 3) Flash attention with RPE bias lookup + online softmax.
// Block 256 = 32 queries x 8 groups; grid (32 qtiles, NH, BB).
// ---------------------------------------------------------------------------
#define QSTRIDE 36

__global__ void __launch_bounds__(256) attn_kernel() {
    __shared__ float sQ[32 * QSTRIDE];
    __shared__ float sK[32 * QSTRIDE];
    __shared__ float sV[32 * QSTRIDE];
    __shared__ float sP[32 * QSTRIDE];
    __shared__ float sTable[TBL];
    __shared__ int sTq[32], sFq[32], sTk[32], sFk[32];

    int tid = threadIdx.x;
    int q = tid >> 3;        // 0..31
    int g = tid & 7;         // 0..7
    int q0 = blockIdx.x << 5;
    int h  = blockIdx.y;
    int b  = blockIdx.z;

    const float* Qg = g_Q + (size_t)((b * NH + h) * NTOK) * DK;
    const float* Kg = g_K + (size_t)((b * NH + h) * NTOK) * DK;
    const float* Vg = g_V + (size_t)((b * NH + h) * NTOK) * DK;
    const int* t_q = dp_tq; const int* f_q = dp_fq;
    const int* t_k = dp_tk; const int* f_k = dp_fk;

    const float* tb = g_table + h * TBL;
    for (int i = tid; i < TBL; i += 256) sTable[i] = tb[i];

    {
        int r = tid >> 3;
        int c = (tid & 7) << 2;
        int qr = q0 + r;
        float4 v = make_float4(0.f, 0.f, 0.f, 0.f);
        if (qr < NTOK) v = *(const float4*)(Qg + (size_t)qr * DK + c);
        const float invs = 0.17677669529663688f;   // 1/sqrt(32)
        v.x *= invs; v.y *= invs; v.z *= invs; v.w *= invs;
        *(float4*)&sQ[r * QSTRIDE + c] = v;
        if (tid < 32) {
            int qi = min(q0 + tid, NTOK - 1);
            sTq[tid] = t_q[qi];
            sFq[tid] = f_q[qi];
        }
    }
    __syncthreads();

    float m_run = -1e30f;
    float l_run = 0.f;
    float4 acc = make_float4(0.f, 0.f, 0.f, 0.f);

    int tq = sTq[q];
    int fq = sFq[q];

    for (int kc = 0; kc < 32; kc++) {
        int k0 = kc << 5;
        __syncthreads();
        {
            int r = tid >> 3;
            int c = (tid & 7) << 2;
            int kr = k0 + r;
            float4 kv = make_float4(0.f, 0.f, 0.f, 0.f);
            float4 vv = make_float4(0.f, 0.f, 0.f, 0.f);
            if (kr < NTOK) {
                kv = *(const float4*)(Kg + (size_t)kr * DK + c);
                vv = *(const float4*)(Vg + (size_t)kr * DK + c);
            }
            *(float4*)&sK[r * QSTRIDE + c] = kv;
            *(float4*)&sV[r * QSTRIDE + c] = vv;
            if (tid < 32) {
                int ki = min(k0 + tid, NTOK - 1);
                sTk[tid] = t_k[ki];
                sFk[tid] = f_k[ki];
            }
        }
        __syncthreads();

        float s0 = 0.f, s1 = 0.f, s2 = 0.f, s3 = 0.f;
        const float4* q4 = (const float4*)&sQ[q * QSTRIDE];
#pragma unroll
        for (int d4 = 0; d4 < 8; d4++) {
            float4 qv = q4[d4];
            float4 k0v = *(const float4*)&sK[(g * 4 + 0) * QSTRIDE + d4 * 4];
            float4 k1v = *(const float4*)&sK[(g * 4 + 1) * QSTRIDE + d4 * 4];
            float4 k2v = *(const float4*)&sK[(g * 4 + 2) * QSTRIDE + d4 * 4];
            float4 k3v = *(const float4*)&sK[(g * 4 + 3) * QSTRIDE + d4 * 4];
            s0 += qv.x * k0v.x + qv.y * k0v.y + qv.z * k0v.z + qv.w * k0v.w;
            s1 += qv.x * k1v.x + qv.y * k1v.y + qv.z * k1v.z + qv.w * k1v.w;
            s2 += qv.x * k2v.x + qv.y * k2v.y + qv.z * k2v.z + qv.w * k2v.w;
            s3 += qv.x * k3v.x + qv.y * k3v.y + qv.z * k3v.z + qv.w * k3v.w;
        }

        float sv[4] = {s0, s1, s2, s3};
#pragma unroll
        for (int j = 0; j < 4; j++) {
            int k = g * 4 + j;
            int dt = tq - sTk[k] + (NT - 1);
            int df = fq - sFk[k] + (NF - 1);
            float bias = sTable[dt * NDF + df];
            sv[j] = (k0 + k < NTOK) ? (sv[j] + bias) : -1e30f;
        }

        float mx = fmaxf(fmaxf(sv[0], sv[1]), fmaxf(sv[2], sv[3]));
#pragma unroll
        for (int off = 1; off < 8; off <<= 1)
            mx = fmaxf(mx, __shfl_xor_sync(0xffffffffu, mx, off));

        float m_new = fmaxf(m_run, mx);
        float corr = __expf(m_run - m_new);
        float p0 = __expf(sv[0] - m_new);
        float p1 = __expf(sv[1] - m_new);
        float p2 = __expf(sv[2] - m_new);
        float p3 = __expf(sv[3] - m_new);
        float ls = p0 + p1 + p2 + p3;
#pragma unroll
        for (int off = 1; off < 8; off <<= 1)
            ls += __shfl_xor_sync(0xffffffffu, ls, off);

        l_run = l_run * corr + ls;
        m_run = m_new;
        acc.x *= corr; acc.y *= corr; acc.z *= corr; acc.w *= corr;

        *(float4*)&sP[q * QSTRIDE + g * 4] = make_float4(p0, p1, p2, p3);
        __syncwarp();

        const float4* p4 = (const float4*)&sP[q * QSTRIDE];
#pragma unroll
        for (int k4 = 0; k4 < 8; k4++) {
            float4 pv = p4[k4];
            float4 v0 = *(const float4*)&sV[(k4 * 4 + 0) * QSTRIDE + g * 4];
            float4 v1 = *(const float4*)&sV[(k4 * 4 + 1) * QSTRIDE + g * 4];
            float4 v2 = *(const float4*)&sV[(k4 * 4 + 2) * QSTRIDE + g * 4];
            float4 v3 = *(const float4*)&sV[(k4 * 4 + 3) * QSTRIDE + g * 4];
            acc.x += pv.x * v0.x + pv.y * v1.x + pv.z * v2.x + pv.w * v3.x;
            acc.y += pv.x * v0.y + pv.y * v1.y + pv.z * v2.y + pv.w * v3.y;
            acc.z += pv.x * v0.z + pv.y * v1.z + pv.z * v2.z + pv.w * v3.z;
            acc.w += pv.x * v0.w + pv.y * v1.w + pv.z * v2.w + pv.w * v3.w;
        }
    }

    int qr = q0 + q;
    if (qr < NTOK) {
        float inv = 1.0f / l_run;
        float4 o = make_float4(acc.x * inv, acc.y * inv, acc.z * inv, acc.w * inv);
        *(float4*)(g_AO + (size_t)(b * NTOK + qr) * DM + h * DK + g * 4) = o;
    }
}

// ---------------------------------------------------------------------------
// Launch — inputs bucketed by SIZE (ordering-agnostic); within-class
// permutation resolved on device by classify_kernel.
// ---------------------------------------------------------------------------
extern "C" void kernel_launch(void* const* d_in, const int* in_sizes, int n_in,
                              void* d_out, int out_size) {
    const void* tok[3] = {0, 0, 0};
    const void* pos[4] = {0, 0, 0, 0};
    const void* wgt[4] = {0, 0, 0, 0};
    const void* wrpe = 0;
    int ntok = 0, npos = 0, nw = 0;
    for (int i = 0; i < n_in; i++) {
        int s = in_sizes[i];
        if (s == MTOT * DM && ntok < 3)      tok[ntok++] = d_in[i];
        else if (s == NTOK && npos < 4)      pos[npos++] = d_in[i];
        else if (s == DM * DM && nw < 4)     wgt[nw++]   = d_in[i];
        else if (s == NH * 32)               wrpe        = d_in[i];
    }
    // Fallback to assumed insertion layout if size-classing failed
    if (ntok != 3 || npos != 4 || nw != 4 || !wrpe) {
        tok[0] = d_in[0]; tok[1] = d_in[1]; tok[2] = d_in[2];
        pos[0] = d_in[3]; pos[1] = d_in[4]; pos[2] = d_in[5]; pos[3] = d_in[6];
        int base = n_in - 5;
        wgt[0] = d_in[base]; wgt[1] = d_in[base + 1];
        wgt[2] = d_in[base + 2]; wgt[3] = d_in[base + 3];
        wrpe = d_in[base + 4];
    }
    float* out = (float*)d_out;

    classify_kernel<<<1, 128>>>(
        (const float*)tok[0], (const float*)tok[1], (const float*)tok[2],
        (const int*)pos[0], (const int*)pos[1], (const int*)pos[2], (const int*)pos[3],
        (const float*)wgt[0], (const float*)wgt[1], (const float*)wgt[2], (const float*)wgt[3],
        (const float*)wrpe);

    bias_table_kernel<<<(NH * TBL + 255) / 256, 256>>>();

    dim3 ggrid(DM / 64, MTOT / 64);
    gemm256<<<ggrid, 256>>>(nullptr, 1);
    gemm256<<<ggrid, 256>>>(nullptr, 2);
    gemm256<<<ggrid, 256>>>(nullptr, 3);

    dim3 agrid((NTOK + 31) / 32, NH, BB);
    attn_kernel<<<agrid, 256>>>();

    gemm256<<<ggrid, 256>>>(out, 0);
}

// round 5
// speedup vs baseline: 3.0847x; 3.0847x over previous
#include <cuda_runtime.h>
#include <math.h>

// Problem constants (fixed by setup_inputs)
#define BB    8
#define NT    14
#define NF    72
#define NTOK  1008          // NT*NF
#define DM    256
#define NH    8
#define DK    32
#define NFREQ 8             // d_rpe/2/2
#define NDT   27            // 2*NT-1
#define NDF   143           // 2*NF-1
#define TBL   (NDT*NDF)     // 3861
#define MTOT  (BB*NTOK)     // 8064
#define BH    (BB*NH)       // 64

// Scratch (device globals; module-static, no runtime allocation)
__device__ float g_table[NH * TBL];
__device__ float g_Q[BH * NTOK * DK];
__device__ float g_K[BH * NTOK * DK];
__device__ float g_V[BH * NTOK * DK];
__device__ float g_AO[MTOT * DM];

// Resolved input pointers (filled by classify_kernel on device)
__device__ const float* dp_qt;
__device__ const float* dp_kt;
__device__ const float* dp_vt;
__device__ const int*   dp_tq;
__device__ const int*   dp_fq;
__device__ const int*   dp_tk;
__device__ const int*   dp_fk;
__device__ const float* dp_Wq;
__device__ const float* dp_Wk;
__device__ const float* dp_Wv;
__device__ const float* dp_Wo;
__device__ const float* dp_Wrpe;

// ---------------------------------------------------------------------------
// 0) Classify inputs by content (ordering-agnostic). See round-4 notes:
//    t_* arrays have max <= 13; f_* arrays have max >= 14 (w.h.p.).
// ---------------------------------------------------------------------------
__global__ void classify_kernel(const float* t0, const float* t1, const float* t2,
                                const int* p0, const int* p1, const int* p2, const int* p3,
                                const float* w0, const float* w1, const float* w2, const float* w3,
                                const float* wr) {
    __shared__ int mres[4];
    int tid = threadIdx.x;
    int w = tid >> 5, lane = tid & 31;
    const int* arr = (w == 0) ? p0 : (w == 1) ? p1 : (w == 2) ? p2 : p3;
    int m = 0;
    for (int i = lane; i < NTOK; i += 32) m = max(m, arr[i]);
#pragma unroll
    for (int off = 16; off > 0; off >>= 1)
        m = max(m, __shfl_xor_sync(0xffffffffu, m, off));
    if (lane == 0) mres[w] = m;
    __syncthreads();
    if (tid == 0) {
        bool T0 = (mres[0] <= NT - 1), T1 = (mres[1] <= NT - 1);
        bool T2 = (mres[2] <= NT - 1), T3 = (mres[3] <= NT - 1);
        if (!T0 && !T1 && T2 && T3) {
            // alphabetical: f_k, f_q, t_k, t_q | k,q,v tokens | W_k,W_o,W_q,W_v
            dp_fk = p0; dp_fq = p1; dp_tk = p2; dp_tq = p3;
            dp_kt = t0; dp_qt = t1; dp_vt = t2;
            dp_Wk = w0; dp_Wo = w1; dp_Wq = w2; dp_Wv = w3;
        } else if (T0 && T1 && !T2 && !T3) {
            // grouped: t_q, t_k, f_q, f_k
            dp_tq = p0; dp_tk = p1; dp_fq = p2; dp_fk = p3;
            dp_qt = t0; dp_kt = t1; dp_vt = t2;
            dp_Wq = w0; dp_Wk = w1; dp_Wv = w2; dp_Wo = w3;
        } else {
            // insertion: t_q, f_q, t_k, f_k
            dp_tq = p0; dp_fq = p1; dp_tk = p2; dp_fk = p3;
            dp_qt = t0; dp_kt = t1; dp_vt = t2;
            dp_Wq = w0; dp_Wk = w1; dp_Wv = w2; dp_Wo = w3;
        }
        dp_Wrpe = wr;
    }
}

// ---------------------------------------------------------------------------
// 1) RPE bias table
// ---------------------------------------------------------------------------
__global__ void bias_table_kernel() {
    int gid = blockIdx.x * blockDim.x + threadIdx.x;
    if (gid >= NH * TBL) return;
    int pos = gid >> 3;
    int h   = gid & 7;
    int dt  = pos / NDF;
    int df  = pos % NDF;
    float pt = (float)(dt - (NT - 1)) / (float)(NT - 1);
    float pf = (float)(df - (NF - 1)) / (float)(NF - 1);
    const float* w = dp_Wrpe + h * 32;
    float acc = 0.f;
    float lg = logf(10000.0f);
#pragma unroll
    for (int j = 0; j < NFREQ; j++) {
        float fr = expf(-lg * (float)j / (float)NFREQ);
        float at = pt * fr;
        float af = pf * fr;
        acc += sinf(at) * w[j];
        acc += cosf(at) * w[NFREQ + j];
        acc += sinf(af) * w[2 * NFREQ + j];
        acc += cosf(af) * w[3 * NFREQ + j];
    }
    g_table[h * TBL + pos] = acc;
}

// ---------------------------------------------------------------------------
// 2) GEMM: C[m][n] = sum_k X[m][k]*W[n][k]. 128(M)x64(N) tiles, 8x4 micro,
//    k-major smem (As transposed at store), FMA-bound (~0.094 LDS/FMA).
//    sel 1/2/3: head-split write to g_Q/K/V; sel 0: row-major to outp.
// ---------------------------------------------------------------------------
__global__ void __launch_bounds__(256) gemm_big(float* __restrict__ outp, int sel) {
    const float* X;
    const float* W;
    if      (sel == 1) { X = dp_qt; W = dp_Wq; }
    else if (sel == 2) { X = dp_kt; W = dp_Wk; }
    else if (sel == 3) { X = dp_vt; W = dp_Wv; }
    else               { X = g_AO;  W = dp_Wo; }

    __shared__ float As[16 * 132];   // [k][m], stride 132
    __shared__ float Bs[16 * 68];    // [k][n], stride 68
    int tid = threadIdx.x;
    int ca = tid & 15;               // col group: cols ca*4..ca*4+3
    int ra = tid >> 4;               // row group: rows ra*4..+3 and 64+ra*4..+3
    int m0 = blockIdx.y << 7;
    int n0 = blockIdx.x << 6;

    float acc[8][4];
#pragma unroll
    for (int i = 0; i < 8; i++)
#pragma unroll
        for (int j = 0; j < 4; j++) acc[i][j] = 0.f;

    for (int k0 = 0; k0 < DM; k0 += 16) {
        __syncthreads();
#pragma unroll
        for (int j = 0; j < 2; j++) {
            int f = tid + j * 256;
            int m = f >> 2, k4 = f & 3;
            float4 v = *(const float4*)(X + (size_t)(m0 + m) * DM + k0 + (k4 << 2));
            As[(k4 * 4 + 0) * 132 + m] = v.x;
            As[(k4 * 4 + 1) * 132 + m] = v.y;
            As[(k4 * 4 + 2) * 132 + m] = v.z;
            As[(k4 * 4 + 3) * 132 + m] = v.w;
        }
        {
            int n = tid >> 2, k4 = tid & 3;
            float4 v = *(const float4*)(W + (size_t)(n0 + n) * DM + k0 + (k4 << 2));
            Bs[(k4 * 4 + 0) * 68 + n] = v.x;
            Bs[(k4 * 4 + 1) * 68 + n] = v.y;
            Bs[(k4 * 4 + 2) * 68 + n] = v.z;
            Bs[(k4 * 4 + 3) * 68 + n] = v.w;
        }
        __syncthreads();
#pragma unroll
        for (int k = 0; k < 16; k++) {
            float4 a0 = *(const float4*)&As[k * 132 + (ra << 2)];
            float4 a1 = *(const float4*)&As[k * 132 + 64 + (ra << 2)];
            float4 b  = *(const float4*)&Bs[k * 68 + (ca << 2)];
            acc[0][0] += a0.x * b.x; acc[0][1] += a0.x * b.y; acc[0][2] += a0.x * b.z; acc[0][3] += a0.x * b.w;
            acc[1][0] += a0.y * b.x; acc[1][1] += a0.y * b.y; acc[1][2] += a0.y * b.z; acc[1][3] += a0.y * b.w;
            acc[2][0] += a0.z * b.x; acc[2][1] += a0.z * b.y; acc[2][2] += a0.z * b.z; acc[2][3] += a0.z * b.w;
            acc[3][0] += a0.w * b.x; acc[3][1] += a0.w * b.y; acc[3][2] += a0.w * b.z; acc[3][3] += a0.w * b.w;
            acc[4][0] += a1.x * b.x; acc[4][1] += a1.x * b.y; acc[4][2] += a1.x * b.z; acc[4][3] += a1.x * b.w;
            acc[5][0] += a1.y * b.x; acc[5][1] += a1.y * b.y; acc[5][2] += a1.y * b.z; acc[5][3] += a1.y * b.w;
            acc[6][0] += a1.z * b.x; acc[6][1] += a1.z * b.y; acc[6][2] += a1.z * b.z; acc[6][3] += a1.z * b.w;
            acc[7][0] += a1.w * b.x; acc[7][1] += a1.w * b.y; acc[7][2] += a1.w * b.z; acc[7][3] += a1.w * b.w;
        }
    }

    int ncol = n0 + (ca << 2);
    if (sel == 0) {
#pragma unroll
        for (int i = 0; i < 8; i++) {
            int m = m0 + ((i < 4) ? (ra * 4 + i) : (64 + ra * 4 + i - 4));
            float4 o = make_float4(acc[i][0], acc[i][1], acc[i][2], acc[i][3]);
            *(float4*)(outp + (size_t)m * DM + ncol) = o;
        }
    } else {
        float* dst = (sel == 1) ? g_Q : (sel == 2) ? g_K : g_V;
        int h = ncol >> 5;
        int d = ncol & 31;
#pragma unroll
        for (int i = 0; i < 8; i++) {
            int m = m0 + ((i < 4) ? (ra * 4 + i) : (64 + ra * 4 + i - 4));
            int b = m / NTOK;
            int nn = m - b * NTOK;
            float4 o = make_float4(acc[i][0], acc[i][1], acc[i][2], acc[i][3]);
            *(float4*)(dst + (size_t)((b * NH + h) * NTOK + nn) * DK + d) = o;
        }
    }
}

// ---------------------------------------------------------------------------
// 3) Flash attention, 64q x 64k tiles. 256 threads = (tx 0..15) x (ty 0..15).
//    Scores: 4q x 4k micro; PV: 4q x 2d micro with V transposed in smem.
//    XOR-swizzled sK/sVT for conflict-free fragment reads.
//    Softmax state replicated across tx via butterfly shuffles.
// ---------------------------------------------------------------------------
__global__ void __launch_bounds__(256) attn_kernel() {
    __shared__ float sQ[64 * 36];     // [q][d] swizzled, stride 36
    __shared__ float sK[64 * 36];     // [k][d] swizzled
    __shared__ float sVT[32 * 68];    // [d][k] swizzled, stride 68
    __shared__ float sP[64 * 68];     // [q][k], stride 68
    __shared__ int sTq[64], sFq[64], sTk[64], sFk[64];

    int tid = threadIdx.x;
    int tx = tid & 15, ty = tid >> 4;
    int q0 = blockIdx.x << 6;
    int h = blockIdx.y, b = blockIdx.z;
    int bh = b * NH + h;

    const float4* Q4 = (const float4*)(g_Q + (size_t)bh * NTOK * DK);
    const float4* K4 = (const float4*)(g_K + (size_t)bh * NTOK * DK);
    const float4* V4 = (const float4*)(g_V + (size_t)bh * NTOK * DK);
    const float* tb = g_table + h * TBL;   // L1-resident gather table

    const float invs = 0.17677669529663688f;   // 1/sqrt(32)
#pragma unroll
    for (int j = 0; j < 2; j++) {
        int f = tid + j * 256;
        int r = f >> 3, c4 = f & 7;
        int qr = q0 + r;
        float4 v = make_float4(0.f, 0.f, 0.f, 0.f);
        if (qr < NTOK) v = Q4[qr * 8 + c4];
        v.x *= invs; v.y *= invs; v.z *= invs; v.w *= invs;
        *(float4*)&sQ[r * 36 + (((c4 ^ ((r >> 2) & 7))) << 2)] = v;
    }
    if (tid < 64) {
        int qi = min(q0 + tid, NTOK - 1);
        sTq[tid] = dp_tq[qi];
        sFq[tid] = dp_fq[qi];
    }
    __syncthreads();

    int tqv[4], fqv[4];
#pragma unroll
    for (int i = 0; i < 4; i++) {
        tqv[i] = sTq[ty * 4 + i];
        fqv[i] = sFq[ty * 4 + i];
    }

    float m_run[4], l_run[4], acc[4][2];
#pragma unroll
    for (int i = 0; i < 4; i++) {
        m_run[i] = -1e30f; l_run[i] = 0.f;
        acc[i][0] = 0.f; acc[i][1] = 0.f;
    }

    for (int kc = 0; kc < 16; kc++) {
        int k0 = kc << 6;
        __syncthreads();   // prior chunk's PV readers done before overwrite
#pragma unroll
        for (int j = 0; j < 2; j++) {
            int f = tid + j * 256;
            int r = f >> 3, c4 = f & 7;
            int kr = k0 + r;
            float4 kv = make_float4(0.f, 0.f, 0.f, 0.f);
            float4 vv = make_float4(0.f, 0.f, 0.f, 0.f);
            if (kr < NTOK) {
                kv = K4[kr * 8 + c4];
                vv = V4[kr * 8 + c4];
            }
            *(float4*)&sK[r * 36 + (((c4 ^ ((r >> 2) & 7))) << 2)] = kv;
            int d0 = c4 << 2;
            int kb = r >> 2, kw = r & 3;
            sVT[(d0 + 0) * 68 + ((kb ^ (((d0 + 0) >> 1) & 7)) << 2) + kw] = vv.x;
            sVT[(d0 + 1) * 68 + ((kb ^ (((d0 + 1) >> 1) & 7)) << 2) + kw] = vv.y;
            sVT[(d0 + 2) * 68 + ((kb ^ (((d0 + 2) >> 1) & 7)) << 2) + kw] = vv.z;
            sVT[(d0 + 3) * 68 + ((kb ^ (((d0 + 3) >> 1) & 7)) << 2) + kw] = vv.w;
        }
        if (tid < 64) {
            int ki = min(k0 + tid, NTOK - 1);
            sTk[tid] = dp_tk[ki];
            sFk[tid] = dp_fk[ki];
        }
        __syncthreads();

        // --- scores: 4x4 ---
        float p[4][4];
#pragma unroll
        for (int i = 0; i < 4; i++)
#pragma unroll
            for (int j = 0; j < 4; j++) p[i][j] = 0.f;

#pragma unroll
        for (int d4 = 0; d4 < 8; d4++) {
            float4 qa[4], kb4[4];
#pragma unroll
            for (int i = 0; i < 4; i++)
                qa[i] = *(const float4*)&sQ[(ty * 4 + i) * 36 + ((d4 ^ (ty & 7)) << 2)];
#pragma unroll
            for (int j = 0; j < 4; j++)
                kb4[j] = *(const float4*)&sK[(tx * 4 + j) * 36 + ((d4 ^ (tx & 7)) << 2)];
#pragma unroll
            for (int i = 0; i < 4; i++)
#pragma unroll
                for (int j = 0; j < 4; j++)
                    p[i][j] += qa[i].x * kb4[j].x + qa[i].y * kb4[j].y +
                               qa[i].z * kb4[j].z + qa[i].w * kb4[j].w;
        }

        // --- bias + mask ---
        int rem = NTOK - k0;
#pragma unroll
        for (int j = 0; j < 4; j++) {
            int kk = tx * 4 + j;
            int tk = sTk[kk], fk = sFk[kk];
            bool valid = kk < rem;
#pragma unroll
            for (int i = 0; i < 4; i++) {
                float bias = tb[(tqv[i] - tk + (NT - 1)) * NDF + (fqv[i] - fk + (NF - 1))];
                p[i][j] = valid ? (p[i][j] + bias) : -1e30f;
            }
        }

        // --- online softmax (state replicated across tx) ---
#pragma unroll
        for (int i = 0; i < 4; i++) {
            float mx = fmaxf(fmaxf(p[i][0], p[i][1]), fmaxf(p[i][2], p[i][3]));
#pragma unroll
            for (int off = 1; off < 16; off <<= 1)
                mx = fmaxf(mx, __shfl_xor_sync(0xffffffffu, mx, off));
            float m_new = fmaxf(m_run[i], mx);
            float corr = __expf(m_run[i] - m_new);
            p[i][0] = __expf(p[i][0] - m_new);
            p[i][1] = __expf(p[i][1] - m_new);
            p[i][2] = __expf(p[i][2] - m_new);
            p[i][3] = __expf(p[i][3] - m_new);
            float ls = p[i][0] + p[i][1] + p[i][2] + p[i][3];
#pragma unroll
            for (int off = 1; off < 16; off <<= 1)
                ls += __shfl_xor_sync(0xffffffffu, ls, off);
            l_run[i] = l_run[i] * corr + ls;
            m_run[i] = m_new;
            acc[i][0] *= corr;
            acc[i][1] *= corr;
            *(float4*)&sP[(ty * 4 + i) * 68 + (tx << 2)] =
                make_float4(p[i][0], p[i][1], p[i][2], p[i][3]);
        }
        __syncthreads();

        // --- PV: 4q x 2d ---
#pragma unroll
        for (int k4 = 0; k4 < 16; k4++) {
            float4 v0 = *(const float4*)&sVT[(tx * 2 + 0) * 68 + ((k4 ^ (tx & 7)) << 2)];
            float4 v1 = *(const float4*)&sVT[(tx * 2 + 1) * 68 + ((k4 ^ (tx & 7)) << 2)];
#pragma unroll
            for (int i = 0; i < 4; i++) {
                float4 pv = *(const float4*)&sP[(ty * 4 + i) * 68 + (k4 << 2)];
                acc[i][0] += pv.x * v0.x + pv.y * v0.y + pv.z * v0.z + pv.w * v0.w;
                acc[i][1] += pv.x * v1.x + pv.y * v1.y + pv.z * v1.z + pv.w * v1.w;
            }
        }
    }

    // epilogue
#pragma unroll
    for (int i = 0; i < 4; i++) {
        int qr = q0 + ty * 4 + i;
        if (qr < NTOK) {
            float inv = 1.0f / l_run[i];
            float2 o = make_float2(acc[i][0] * inv, acc[i][1] * inv);
            *(float2*)&g_AO[(size_t)(b * NTOK + qr) * DM + h * DK + tx * 2] = o;
        }
    }
}

// ---------------------------------------------------------------------------
// Launch
// ---------------------------------------------------------------------------
extern "C" void kernel_launch(void* const* d_in, const int* in_sizes, int n_in,
                              void* d_out, int out_size) {
    const void* tok[3] = {0, 0, 0};
    const void* pos[4] = {0, 0, 0, 0};
    const void* wgt[4] = {0, 0, 0, 0};
    const void* wrpe = 0;
    int ntok = 0, npos = 0, nw = 0;
    for (int i = 0; i < n_in; i++) {
        int s = in_sizes[i];
        if (s == MTOT * DM && ntok < 3)      tok[ntok++] = d_in[i];
        else if (s == NTOK && npos < 4)      pos[npos++] = d_in[i];
        else if (s == DM * DM && nw < 4)     wgt[nw++]   = d_in[i];
        else if (s == NH * 32)               wrpe        = d_in[i];
    }
    if (ntok != 3 || npos != 4 || nw != 4 || !wrpe) {
        tok[0] = d_in[0]; tok[1] = d_in[1]; tok[2] = d_in[2];
        pos[0] = d_in[3]; pos[1] = d_in[4]; pos[2] = d_in[5]; pos[3] = d_in[6];
        int base = n_in - 5;
        wgt[0] = d_in[base]; wgt[1] = d_in[base + 1];
        wgt[2] = d_in[base + 2]; wgt[3] = d_in[base + 3];
        wrpe = d_in[base + 4];
    }
    float* out = (float*)d_out;

    classify_kernel<<<1, 128>>>(
        (const float*)tok[0], (const float*)tok[1], (const float*)tok[2],
        (const int*)pos[0], (const int*)pos[1], (const int*)pos[2], (const int*)pos[3],
        (const float*)wgt[0], (const float*)wgt[1], (const float*)wgt[2], (const float*)wgt[3],
        (const float*)wrpe);

    bias_table_kernel<<<(NH * TBL + 255) / 256, 256>>>();

    dim3 ggrid(DM / 64, MTOT / 128);          // (4, 63)
    gemm_big<<<ggrid, 256>>>(nullptr, 1);
    gemm_big<<<ggrid, 256>>>(nullptr, 2);
    gemm_big<<<ggrid, 256>>>(nullptr, 3);

    dim3 agrid((NTOK + 63) / 64, NH, BB);     // (16, 8, 8)
    attn_kernel<<<agrid, 256>>>();

    gemm_big<<<ggrid, 256>>>(out, 0);
}

// round 6
// speedup vs baseline: 4.5888x; 1.4876x over previous
#include <cuda_runtime.h>
#include <math.h>

// Problem constants (fixed by setup_inputs)
#define BB    8
#define NT    14
#define NF    72
#define NTOK  1008          // NT*NF
#define DM    256
#define NH    8
#define DK    32
#define NFREQ 8             // d_rpe/2/2
#define NDT   27            // 2*NT-1
#define NDF   143           // 2*NF-1
#define TBL   (NDT*NDF)     // 3861
#define MTOT  (BB*NTOK)     // 8064
#define BH    (BB*NH)       // 64

// Scratch (device globals; module-static, no runtime allocation)
__device__ float g_table[NH * TBL];
__device__ float g_Q[BH * NTOK * DK];
__device__ float g_K[BH * NTOK * DK];
__device__ float g_V[BH * NTOK * DK];
__device__ float g_AO[MTOT * DM];

// Resolved input pointers (filled by classify_kernel on device)
__device__ const float* dp_qt;
__device__ const float* dp_kt;
__device__ const float* dp_vt;
__device__ const int*   dp_tq;
__device__ const int*   dp_fq;
__device__ const int*   dp_tk;
__device__ const int*   dp_fk;
__device__ const float* dp_Wq;
__device__ const float* dp_Wk;
__device__ const float* dp_Wv;
__device__ const float* dp_Wo;
__device__ const float* dp_Wrpe;

// ---------------------------------------------------------------------------
// tf32 helpers
// ---------------------------------------------------------------------------
__device__ __forceinline__ unsigned tf32u(float f) {
    unsigned u;
    asm("cvt.rna.tf32.f32 %0, %1;" : "=r"(u) : "f"(f));
    return u;
}

__device__ __forceinline__ void mma_tf32(float4& d, unsigned a0, unsigned a1,
                                         unsigned a2, unsigned a3,
                                         unsigned b0, unsigned b1) {
    asm("mma.sync.aligned.m16n8k8.row.col.f32.tf32.tf32.f32 "
        "{%0,%1,%2,%3},{%4,%5,%6,%7},{%8,%9},{%0,%1,%2,%3};"
        : "+f"(d.x), "+f"(d.y), "+f"(d.z), "+f"(d.w)
        : "r"(a0), "r"(a1), "r"(a2), "r"(a3), "r"(b0), "r"(b1));
}

// ---------------------------------------------------------------------------
// 0) Classify inputs by content (ordering-agnostic).
// ---------------------------------------------------------------------------
__global__ void classify_kernel(const float* t0, const float* t1, const float* t2,
                                const int* p0, const int* p1, const int* p2, const int* p3,
                                const float* w0, const float* w1, const float* w2, const float* w3,
                                const float* wr) {
    __shared__ int mres[4];
    int tid = threadIdx.x;
    int w = tid >> 5, lane = tid & 31;
    const int* arr = (w == 0) ? p0 : (w == 1) ? p1 : (w == 2) ? p2 : p3;
    int m = 0;
    for (int i = lane; i < NTOK; i += 32) m = max(m, arr[i]);
#pragma unroll
    for (int off = 16; off > 0; off >>= 1)
        m = max(m, __shfl_xor_sync(0xffffffffu, m, off));
    if (lane == 0) mres[w] = m;
    __syncthreads();
    if (tid == 0) {
        bool T0 = (mres[0] <= NT - 1), T1 = (mres[1] <= NT - 1);
        bool T2 = (mres[2] <= NT - 1), T3 = (mres[3] <= NT - 1);
        if (!T0 && !T1 && T2 && T3) {
            dp_fk = p0; dp_fq = p1; dp_tk = p2; dp_tq = p3;
            dp_kt = t0; dp_qt = t1; dp_vt = t2;
            dp_Wk = w0; dp_Wo = w1; dp_Wq = w2; dp_Wv = w3;
        } else if (T0 && T1 && !T2 && !T3) {
            dp_tq = p0; dp_tk = p1; dp_fq = p2; dp_fk = p3;
            dp_qt = t0; dp_kt = t1; dp_vt = t2;
            dp_Wq = w0; dp_Wk = w1; dp_Wv = w2; dp_Wo = w3;
        } else {
            dp_tq = p0; dp_fq = p1; dp_tk = p2; dp_fk = p3;
            dp_qt = t0; dp_kt = t1; dp_vt = t2;
            dp_Wq = w0; dp_Wk = w1; dp_Wv = w2; dp_Wo = w3;
        }
        dp_Wrpe = wr;
    }
}

// ---------------------------------------------------------------------------
// 1) RPE bias table
// ---------------------------------------------------------------------------
__global__ void bias_table_kernel() {
    int gid = blockIdx.x * blockDim.x + threadIdx.x;
    if (gid >= NH * TBL) return;
    int pos = gid >> 3;
    int h   = gid & 7;
    int dt  = pos / NDF;
    int df  = pos % NDF;
    float pt = (float)(dt - (NT - 1)) / (float)(NT - 1);
    float pf = (float)(df - (NF - 1)) / (float)(NF - 1);
    const float* w = dp_Wrpe + h * 32;
    float acc = 0.f;
    float lg = logf(10000.0f);
#pragma unroll
    for (int j = 0; j < NFREQ; j++) {
        float fr = expf(-lg * (float)j / (float)NFREQ);
        float at = pt * fr;
        float af = pf * fr;
        acc += sinf(at) * w[j];
        acc += cosf(at) * w[NFREQ + j];
        acc += sinf(af) * w[2 * NFREQ + j];
        acc += cosf(af) * w[3 * NFREQ + j];
    }
    g_table[h * TBL + pos] = acc;
}

// ---------------------------------------------------------------------------
// 2) GEMM (unchanged from round 5): 128x64 tiles, 8x4 micro.
// ---------------------------------------------------------------------------
__global__ void __launch_bounds__(256) gemm_big(float* __restrict__ outp, int sel) {
    const float* X;
    const float* W;
    if      (sel == 1) { X = dp_qt; W = dp_Wq; }
    else if (sel == 2) { X = dp_kt; W = dp_Wk; }
    else if (sel == 3) { X = dp_vt; W = dp_Wv; }
    else               { X = g_AO;  W = dp_Wo; }

    __shared__ float As[16 * 132];
    __shared__ float Bs[16 * 68];
    int tid = threadIdx.x;
    int ca = tid & 15;
    int ra = tid >> 4;
    int m0 = blockIdx.y << 7;
    int n0 = blockIdx.x << 6;

    float acc[8][4];
#pragma unroll
    for (int i = 0; i < 8; i++)
#pragma unroll
        for (int j = 0; j < 4; j++) acc[i][j] = 0.f;

    for (int k0 = 0; k0 < DM; k0 += 16) {
        __syncthreads();
#pragma unroll
        for (int j = 0; j < 2; j++) {
            int f = tid + j * 256;
            int m = f >> 2, k4 = f & 3;
            float4 v = *(const float4*)(X + (size_t)(m0 + m) * DM + k0 + (k4 << 2));
            As[(k4 * 4 + 0) * 132 + m] = v.x;
            As[(k4 * 4 + 1) * 132 + m] = v.y;
            As[(k4 * 4 + 2) * 132 + m] = v.z;
            As[(k4 * 4 + 3) * 132 + m] = v.w;
        }
        {
            int n = tid >> 2, k4 = tid & 3;
            float4 v = *(const float4*)(W + (size_t)(n0 + n) * DM + k0 + (k4 << 2));
            Bs[(k4 * 4 + 0) * 68 + n] = v.x;
            Bs[(k4 * 4 + 1) * 68 + n] = v.y;
            Bs[(k4 * 4 + 2) * 68 + n] = v.z;
            Bs[(k4 * 4 + 3) * 68 + n] = v.w;
        }
        __syncthreads();
#pragma unroll
        for (int k = 0; k < 16; k++) {
            float4 a0 = *(const float4*)&As[k * 132 + (ra << 2)];
            float4 a1 = *(const float4*)&As[k * 132 + 64 + (ra << 2)];
            float4 b  = *(const float4*)&Bs[k * 68 + (ca << 2)];
            acc[0][0] += a0.x * b.x; acc[0][1] += a0.x * b.y; acc[0][2] += a0.x * b.z; acc[0][3] += a0.x * b.w;
            acc[1][0] += a0.y * b.x; acc[1][1] += a0.y * b.y; acc[1][2] += a0.y * b.z; acc[1][3] += a0.y * b.w;
            acc[2][0] += a0.z * b.x; acc[2][1] += a0.z * b.y; acc[2][2] += a0.z * b.z; acc[2][3] += a0.z * b.w;
            acc[3][0] += a0.w * b.x; acc[3][1] += a0.w * b.y; acc[3][2] += a0.w * b.z; acc[3][3] += a0.w * b.w;
            acc[4][0] += a1.x * b.x; acc[4][1] += a1.x * b.y; acc[4][2] += a1.x * b.z; acc[4][3] += a1.x * b.w;
            acc[5][0] += a1.y * b.x; acc[5][1] += a1.y * b.y; acc[5][2] += a1.y * b.z; acc[5][3] += a1.y * b.w;
            acc[6][0] += a1.z * b.x; acc[6][1] += a1.z * b.y; acc[6][2] += a1.z * b.z; acc[6][3] += a1.z * b.w;
            acc[7][0] += a1.w * b.x; acc[7][1] += a1.w * b.y; acc[7][2] += a1.w * b.z; acc[7][3] += a1.w * b.w;
        }
    }

    int ncol = n0 + (ca << 2);
    if (sel == 0) {
#pragma unroll
        for (int i = 0; i < 8; i++) {
            int m = m0 + ((i < 4) ? (ra * 4 + i) : (64 + ra * 4 + i - 4));
            float4 o = make_float4(acc[i][0], acc[i][1], acc[i][2], acc[i][3]);
            *(float4*)(outp + (size_t)m * DM + ncol) = o;
        }
    } else {
        float* dst = (sel == 1) ? g_Q : (sel == 2) ? g_K : g_V;
        int h = ncol >> 5;
        int d = ncol & 31;
#pragma unroll
        for (int i = 0; i < 8; i++) {
            int m = m0 + ((i < 4) ? (ra * 4 + i) : (64 + ra * 4 + i - 4));
            int b = m / NTOK;
            int nn = m - b * NTOK;
            float4 o = make_float4(acc[i][0], acc[i][1], acc[i][2], acc[i][3]);
            *(float4*)(dst + (size_t)((b * NH + h) * NTOK + nn) * DK + d) = o;
        }
    }
}

// ---------------------------------------------------------------------------
// 3) Flash attention with tf32 mma.sync (m16n8k8).
//    Block 256 thr = 8 warps: warp grid 4(q:16 rows) x 2(keys/dims:32).
//    64q x 64k tiles; Q fragments register-resident for all 16 chunks.
// ---------------------------------------------------------------------------
__global__ void __launch_bounds__(256) attn_kernel() {
    // sPQ: Q staging (stride 36, prologue) then P exchange (stride 68, loop)
    __shared__ __align__(16) unsigned sPQ[64 * 68];
    __shared__ __align__(16) unsigned sKb[64 * 36];
    __shared__ __align__(16) unsigned sVb[64 * 40];
    __shared__ float sRedM[2][64];
    __shared__ float sRedS[2][64];
    __shared__ int sKoff[64];
    __shared__ int sTq[64], sFq[64];

    int tid = threadIdx.x;
    int lane = tid & 31;
    int w = tid >> 5;
    int wm = w >> 1;           // 0..3 -> q rows wm*16..+15
    int wn = w & 1;            // 0..1 -> key/dim half
    int r4 = lane >> 2;        // 0..7
    int cl = lane & 3;         // 0..3
    int q0 = blockIdx.x << 6;
    int h = blockIdx.y, b = blockIdx.z;
    int bh = b * NH + h;

    const float4* Q4 = (const float4*)(g_Q + (size_t)bh * NTOK * DK);
    const float4* K4 = (const float4*)(g_K + (size_t)bh * NTOK * DK);
    const float4* V4 = (const float4*)(g_V + (size_t)bh * NTOK * DK);
    const float* tb = g_table + h * TBL;

    // --- stage Q (scaled, tf32) into sPQ with stride 36 ---
    const float invs = 0.17677669529663688f;   // 1/sqrt(32)
#pragma unroll
    for (int j = 0; j < 2; j++) {
        int f = tid + j * 256;
        int r = f >> 3, c4 = f & 7;
        int qr = q0 + r;
        float4 v = make_float4(0.f, 0.f, 0.f, 0.f);
        if (qr < NTOK) v = Q4[qr * 8 + c4];
        unsigned* dst = &sPQ[r * 36 + (c4 << 2)];
        dst[0] = tf32u(v.x * invs);
        dst[1] = tf32u(v.y * invs);
        dst[2] = tf32u(v.z * invs);
        dst[3] = tf32u(v.w * invs);
    }
    if (tid < 64) {
        int qi = min(q0 + tid, NTOK - 1);
        sTq[tid] = dp_tq[qi];
        sFq[tid] = dp_fq[qi];
    }
    __syncthreads();

    // --- extract Q fragments (held for all chunks) ---
    unsigned qf[4][4];
#pragma unroll
    for (int ks = 0; ks < 4; ks++) {
        int dc = ks * 8 + cl;
        qf[ks][0] = sPQ[(wm * 16 + r4) * 36 + dc];
        qf[ks][1] = sPQ[(wm * 16 + r4 + 8) * 36 + dc];
        qf[ks][2] = sPQ[(wm * 16 + r4) * 36 + dc + 4];
        qf[ks][3] = sPQ[(wm * 16 + r4 + 8) * 36 + dc + 4];
    }
    int row0 = wm * 16 + r4;
    int row1 = row0 + 8;
    int qoff0 = sTq[row0] * NDF + sFq[row0] + (NT - 1) * NDF + (NF - 1);
    int qoff1 = sTq[row1] * NDF + sFq[row1] + (NT - 1) * NDF + (NF - 1);

    float m0r = -1e30f, m1r = -1e30f, l0r = 0.f, l1r = 0.f;
    float4 o0 = make_float4(0.f, 0.f, 0.f, 0.f);
    float4 o1 = make_float4(0.f, 0.f, 0.f, 0.f);

    for (int kc = 0; kc < 16; kc++) {
        int k0 = kc << 6;
        __syncthreads();   // prior chunk PV readers done before KV overwrite
#pragma unroll
        for (int j = 0; j < 2; j++) {
            int f = tid + j * 256;
            int r = f >> 3, c4 = f & 7;
            int kr = k0 + r;
            float4 kv = make_float4(0.f, 0.f, 0.f, 0.f);
            float4 vv = make_float4(0.f, 0.f, 0.f, 0.f);
            if (kr < NTOK) {
                kv = K4[kr * 8 + c4];
                vv = V4[kr * 8 + c4];
            }
            unsigned* dk = &sKb[r * 36 + (c4 << 2)];
            dk[0] = tf32u(kv.x); dk[1] = tf32u(kv.y);
            dk[2] = tf32u(kv.z); dk[3] = tf32u(kv.w);
            unsigned* dv = &sVb[r * 40 + (c4 << 2)];
            dv[0] = tf32u(vv.x); dv[1] = tf32u(vv.y);
            dv[2] = tf32u(vv.z); dv[3] = tf32u(vv.w);
        }
        if (tid < 64) {
            int ki = min(k0 + tid, NTOK - 1);
            sKoff[tid] = dp_tk[ki] * NDF + dp_fk[ki];
        }
        __syncthreads();

        // --- scores: S = Q K^T (per warp: 16q x 32k) ---
        float4 c[4];
#pragma unroll
        for (int nt = 0; nt < 4; nt++) c[nt] = make_float4(0.f, 0.f, 0.f, 0.f);
#pragma unroll
        for (int nt = 0; nt < 4; nt++) {
            int key = wn * 32 + nt * 8 + r4;
#pragma unroll
            for (int ks = 0; ks < 4; ks++) {
                int dd = ks * 8 + cl;
                unsigned b0 = sKb[key * 36 + dd];
                unsigned b1 = sKb[key * 36 + dd + 4];
                mma_tf32(c[nt], qf[ks][0], qf[ks][1], qf[ks][2], qf[ks][3], b0, b1);
            }
        }

        // --- bias + mask ---
        int rem = NTOK - k0;
#pragma unroll
        for (int nt = 0; nt < 4; nt++) {
            int col0 = wn * 32 + nt * 8 + 2 * cl;
            int ko0 = sKoff[col0], ko1 = sKoff[col0 + 1];
            bool v0 = col0 < rem, v1 = col0 + 1 < rem;
            c[nt].x = v0 ? (c[nt].x + tb[qoff0 - ko0]) : -1e30f;
            c[nt].y = v1 ? (c[nt].y + tb[qoff0 - ko1]) : -1e30f;
            c[nt].z = v0 ? (c[nt].z + tb[qoff1 - ko0]) : -1e30f;
            c[nt].w = v1 ? (c[nt].w + tb[qoff1 - ko1]) : -1e30f;
        }

        // --- row max (within warp: 4 lanes own a row) ---
        float mx0 = fmaxf(fmaxf(c[0].x, c[0].y), fmaxf(c[1].x, c[1].y));
        mx0 = fmaxf(mx0, fmaxf(fmaxf(c[2].x, c[2].y), fmaxf(c[3].x, c[3].y)));
        float mx1 = fmaxf(fmaxf(c[0].z, c[0].w), fmaxf(c[1].z, c[1].w));
        mx1 = fmaxf(mx1, fmaxf(fmaxf(c[2].z, c[2].w), fmaxf(c[3].z, c[3].w)));
        mx0 = fmaxf(mx0, __shfl_xor_sync(0xffffffffu, mx0, 1));
        mx0 = fmaxf(mx0, __shfl_xor_sync(0xffffffffu, mx0, 2));
        mx1 = fmaxf(mx1, __shfl_xor_sync(0xffffffffu, mx1, 1));
        mx1 = fmaxf(mx1, __shfl_xor_sync(0xffffffffu, mx1, 2));
        if (cl == 0) {
            sRedM[wn][row0] = mx0;
            sRedM[wn][row1] = mx1;
        }
        __syncthreads();
        float M0 = fmaxf(sRedM[0][row0], sRedM[1][row0]);
        float M1 = fmaxf(sRedM[0][row1], sRedM[1][row1]);
        float mn0 = fmaxf(m0r, M0), mn1 = fmaxf(m1r, M1);
        float corr0 = __expf(m0r - mn0), corr1 = __expf(m1r - mn1);
        m0r = mn0; m1r = mn1;

        float s0 = 0.f, s1 = 0.f;
#pragma unroll
        for (int nt = 0; nt < 4; nt++) {
            c[nt].x = __expf(c[nt].x - mn0);
            c[nt].y = __expf(c[nt].y - mn0);
            c[nt].z = __expf(c[nt].z - mn1);
            c[nt].w = __expf(c[nt].w - mn1);
            s0 += c[nt].x + c[nt].y;
            s1 += c[nt].z + c[nt].w;
        }
        s0 += __shfl_xor_sync(0xffffffffu, s0, 1);
        s0 += __shfl_xor_sync(0xffffffffu, s0, 2);
        s1 += __shfl_xor_sync(0xffffffffu, s1, 1);
        s1 += __shfl_xor_sync(0xffffffffu, s1, 2);
        if (cl == 0) {
            sRedS[wn][row0] = s0;
            sRedS[wn][row1] = s1;
        }
        // write P (tf32 bits) to sPQ with stride 68
#pragma unroll
        for (int nt = 0; nt < 4; nt++) {
            int col0 = wn * 32 + nt * 8 + 2 * cl;
            uint2 pa; pa.x = tf32u(c[nt].x); pa.y = tf32u(c[nt].y);
            uint2 pb; pb.x = tf32u(c[nt].z); pb.y = tf32u(c[nt].w);
            *(uint2*)&sPQ[row0 * 68 + col0] = pa;
            *(uint2*)&sPQ[row1 * 68 + col0] = pb;
        }
        __syncthreads();

        float l0t = sRedS[0][row0] + sRedS[1][row0];
        float l1t = sRedS[0][row1] + sRedS[1][row1];
        l0r = l0r * corr0 + l0t;
        l1r = l1r * corr1 + l1t;
        o0.x *= corr0; o0.y *= corr0; o0.z *= corr1; o0.w *= corr1;
        o1.x *= corr0; o1.y *= corr0; o1.z *= corr1; o1.w *= corr1;

        // --- PV: O += P V (per warp: 16q x 16d) ---
#pragma unroll
        for (int ks = 0; ks < 8; ks++) {
            int kcidx = ks * 8 + cl;
            unsigned a0 = sPQ[row0 * 68 + kcidx];
            unsigned a1 = sPQ[row1 * 68 + kcidx];
            unsigned a2 = sPQ[row0 * 68 + kcidx + 4];
            unsigned a3 = sPQ[row1 * 68 + kcidx + 4];
            {
                int dcol = wn * 16 + r4;
                unsigned b0 = sVb[kcidx * 40 + dcol];
                unsigned b1 = sVb[(kcidx + 4) * 40 + dcol];
                mma_tf32(o0, a0, a1, a2, a3, b0, b1);
            }
            {
                int dcol = wn * 16 + 8 + r4;
                unsigned b0 = sVb[kcidx * 40 + dcol];
                unsigned b1 = sVb[(kcidx + 4) * 40 + dcol];
                mma_tf32(o1, a0, a1, a2, a3, b0, b1);
            }
        }
    }

    // --- epilogue ---
    float inv0 = 1.0f / l0r, inv1 = 1.0f / l1r;
    int qr0 = q0 + row0, qr1 = q0 + row1;
    int dbase = h * DK + wn * 16 + 2 * cl;
    if (qr0 < NTOK) {
        *(float2*)&g_AO[(size_t)(b * NTOK + qr0) * DM + dbase] =
            make_float2(o0.x * inv0, o0.y * inv0);
        *(float2*)&g_AO[(size_t)(b * NTOK + qr0) * DM + dbase + 8] =
            make_float2(o1.x * inv0, o1.y * inv0);
    }
    if (qr1 < NTOK) {
        *(float2*)&g_AO[(size_t)(b * NTOK + qr1) * DM + dbase] =
            make_float2(o0.z * inv1, o0.w * inv1);
        *(float2*)&g_AO[(size_t)(b * NTOK + qr1) * DM + dbase + 8] =
            make_float2(o1.z * inv1, o1.w * inv1);
    }
}

// ---------------------------------------------------------------------------
// Launch
// ---------------------------------------------------------------------------
extern "C" void kernel_launch(void* const* d_in, const int* in_sizes, int n_in,
                              void* d_out, int out_size) {
    const void* tok[3] = {0, 0, 0};
    const void* pos[4] = {0, 0, 0, 0};
    const void* wgt[4] = {0, 0, 0, 0};
    const void* wrpe = 0;
    int ntok = 0, npos = 0, nw = 0;
    for (int i = 0; i < n_in; i++) {
        int s = in_sizes[i];
        if (s == MTOT * DM && ntok < 3)      tok[ntok++] = d_in[i];
        else if (s == NTOK && npos < 4)      pos[npos++] = d_in[i];
        else if (s == DM * DM && nw < 4)     wgt[nw++]   = d_in[i];
        else if (s == NH * 32)               wrpe        = d_in[i];
    }
    if (ntok != 3 || npos != 4 || nw != 4 || !wrpe) {
        tok[0] = d_in[0]; tok[1] = d_in[1]; tok[2] = d_in[2];
        pos[0] = d_in[3]; pos[1] = d_in[4]; pos[2] = d_in[5]; pos[3] = d_in[6];
        int base = n_in - 5;
        wgt[0] = d_in[base]; wgt[1] = d_in[base + 1];
        wgt[2] = d_in[base + 2]; wgt[3] = d_in[base + 3];
        wrpe = d_in[base + 4];
    }
    float* out = (float*)d_out;

    classify_kernel<<<1, 128>>>(
        (const float*)tok[0], (const float*)tok[1], (const float*)tok[2],
        (const int*)pos[0], (const int*)pos[1], (const int*)pos[2], (const int*)pos[3],
        (const float*)wgt[0], (const float*)wgt[1], (const float*)wgt[2], (const float*)wgt[3],
        (const float*)wrpe);

    bias_table_kernel<<<(NH * TBL + 255) / 256, 256>>>();

    dim3 ggrid(DM / 64, MTOT / 128);          // (4, 63)
    gemm_big<<<ggrid, 256>>>(nullptr, 1);
    gemm_big<<<ggrid, 256>>>(nullptr, 2);
    gemm_big<<<ggrid, 256>>>(nullptr, 3);

    dim3 agrid((NTOK + 63) / 64, NH, BB);     // (16, 8, 8)
    attn_kernel<<<agrid, 256>>>();

    gemm_big<<<ggrid, 256>>>(out, 0);
}